// round 12
// baseline (speedup 1.0000x reference)
#include <cuda_runtime.h>

// GlobalFilter: y = irfft2(rfft2(x, ortho) * W, ortho)
// x: [128,14,14,768] f32, W: [14,8,768,2] f32.
// R12 = R11 + (h,14-h) pair-slot smem layout: every slot is 16B holding
//       (F[j], F[14-j]) -> pass A stores pairs (STS.128), pass B loads/stores
//       pairs (LDS/STS.128), pass C loads pairs. ~46% fewer smem instructions,
//       same bytes, same math (double-folded DFTs), same occupancy point.

#define CC  768
#define CB  32
#define NTH 256

typedef unsigned long long ull;

__device__ __forceinline__ ull pk(float lo, float hi) {
    ull r; asm("mov.b64 %0, {%1,%2};" : "=l"(r) : "f"(lo), "f"(hi)); return r;
}
__device__ __forceinline__ void upk(ull v, float& lo, float& hi) {
    asm("mov.b64 {%0,%1}, %2;" : "=f"(lo), "=f"(hi) : "l"(v));
}
__device__ __forceinline__ ull swp(ull v) {
    float lo, hi; upk(v, lo, hi); return pk(hi, lo);
}
__device__ __forceinline__ ull f2fma(ull a, ull b, ull c) {
    ull d; asm("fma.rn.f32x2 %0, %1, %2, %3;" : "=l"(d) : "l"(a), "l"(b), "l"(c)); return d;
}
__device__ __forceinline__ ull f2add(ull a, ull b) {
    ull d; asm("add.rn.f32x2 %0, %1, %2;" : "=l"(d) : "l"(a), "l"(b)); return d;
}
__device__ __forceinline__ ull f2sub(ull a, ull b) {
    ull d; asm("sub.rn.f32x2 %0, %1, %2;" : "=l"(d) : "l"(a), "l"(b)); return d;
}
__host__ __device__ constexpr ull pkc(float lo, float hi) {
    return (ull)__builtin_bit_cast(unsigned int, lo)
         | ((ull)__builtin_bit_cast(unsigned int, hi) << 32);
}
#define CP(v) pkc(v, v)
__device__ __forceinline__ ull cmulw(ull X, ull w) {
    float xr, xi, wr, wi;
    upk(X, xr, xi); upk(w, wr, wi);
    return pk(fmaf(-xi, wi, xr * wr), fmaf(xi, wr, xr * wi));
}
__device__ __forceinline__ void stcs(float* p, float v) {
    asm volatile("st.global.cs.f32 [%0], %1;" :: "l"(p), "f"(v) : "memory");
}

#define DEF_TWIDDLES \
    constexpr float COS14[14] = { \
         1.0f,                 0.9009688679024191f,  0.6234898018587336f, \
         0.22252093395631445f,-0.22252093395631445f,-0.6234898018587336f, \
        -0.9009688679024191f, -1.0f,                -0.9009688679024191f, \
        -0.6234898018587336f, -0.22252093395631445f, 0.22252093395631445f, \
         0.6234898018587336f,  0.9009688679024191f }; \
    constexpr float SIN14[14] = { \
         0.0f,                 0.43388373911755823f, 0.7818314824680298f, \
         0.9749279121818236f,  0.9749279121818236f,  0.7818314824680298f, \
         0.43388373911755823f, 0.0f,                -0.43388373911755823f, \
        -0.7818314824680298f, -0.9749279121818236f, -0.9749279121818236f, \
        -0.7818314824680298f, -0.43388373911755823f }

// Double-folded rfft of one row of x over W; writes 8 packed (re,im) results.
__device__ __forceinline__ void rfft_row(const float* __restrict__ xb,
                                         int h, ull F[8])
{
    DEF_TWIDDLES;
    float xv[14];
    #pragma unroll
    for (int w = 0; w < 14; ++w)
        xv[w] = __ldg(&xb[(h * 14 + w) * CC]);
    ull eo[7];
    #pragma unroll
    for (int j = 1; j <= 6; ++j)
        eo[j] = pk(xv[j] + xv[14 - j], xv[j] - xv[14 - j]);
    const float be = xv[0] + xv[7], bo = xv[0] - xv[7];
    ull eoP[4], eoM[4];
    #pragma unroll
    for (int j = 1; j <= 3; ++j) {
        eoP[j] = f2fma(eo[7 - j], pkc( 1.f, -1.f), eo[j]);
        eoM[j] = f2fma(eo[7 - j], pkc(-1.f,  1.f), eo[j]);
    }
    #pragma unroll
    for (int kw = 0; kw < 8; ++kw) {
        ull acc = pk((kw & 1) ? bo : be, 0.f);
        #pragma unroll
        for (int j = 1; j <= 3; ++j) {
            const int m = (kw * j) % 14;
            acc = f2fma((kw & 1) ? eoM[j] : eoP[j],
                        pkc(COS14[m], -SIN14[m]), acc);
        }
        F[kw] = acc;
    }
}

// Double-folded c2r of one row of Y1 over W + streaming store (scale folded).
__device__ __forceinline__ void c2r_row(float* __restrict__ yb,
                                        int h, const ull yv[8])
{
    DEF_TWIDDLES;
    constexpr float INV98  = 1.0f / 98.0f;
    constexpr float INV196 = 1.0f / 196.0f;
    float yr0, yi0, yr7, yi7;
    upk(yv[0], yr0, yi0); upk(yv[7], yr7, yi7);
    const float b0 = yr0 * INV196, b7 = yr7 * INV196;
    const float bse_e = b0 + b7, bse_o = b0 - b7;
    ull yP[4], yM[4];
    #pragma unroll
    for (int kw = 1; kw <= 3; ++kw) {
        yP[kw] = f2fma(yv[7 - kw], pkc( 1.f, -1.f), yv[kw]);
        yM[kw] = f2fma(yv[7 - kw], pkc(-1.f,  1.f), yv[kw]);
    }
    #pragma unroll
    for (int w = 0; w < 8; ++w) {
        ull acc = pk((w & 1) ? bse_o : bse_e, 0.f);  // (C, S)
        #pragma unroll
        for (int kw = 1; kw <= 3; ++kw) {
            const int m = (kw * w) % 14;
            acc = f2fma((w & 1) ? yM[kw] : yP[kw],
                        pkc(COS14[m] * INV98, SIN14[m] * INV98), acc);
        }
        float Cv, Sv; upk(acc, Cv, Sv);
        stcs(&yb[(h * 14 + w) * CC], Cv - Sv);
        if (w >= 1 && w <= 6)
            stcs(&yb[(h * 14 + 14 - w) * CC], Cv + Sv);
    }
}

__global__ __launch_bounds__(NTH, 4)
void gfilter_kernel(const float* __restrict__ x,
                    const float* __restrict__ wt,
                    float* __restrict__ y)
{
    DEF_TWIDDLES;
    // 56 pair-slots x 32 channels, 16B each. Slot s = p*8 + kw:
    //   p=0      -> (F[0],  F[7])
    //   p=1..6   -> (F[p],  F[14-p])
    extern __shared__ ulonglong2 sbuf[];

    const int tid  = threadIdx.x;
    const int cl   = tid & 31;
    const int role = tid >> 5;      // 0..7, one warp per role
    const int b    = blockIdx.y;
    const int c    = blockIdx.x * CB + cl;

    ulonglong2* bufc = sbuf + cl;   // index: slot*32
    const int base = (b * 196) * CC + c;
    const float* xb = x + base;

    const int hA = role;                         // pair p = role (0..6)
    const int hB = (role == 0) ? 7 : 14 - role;

    // ---- Pass A: rfft over W for both rows of pair p, store 16B pairs ------
    if (role < 7) {
        ull FA[8], FB[8];
        rfft_row(xb, hA, FA);
        rfft_row(xb, hB, FB);
        #pragma unroll
        for (int kw = 0; kw < 8; ++kw)
            bufc[(role * 8 + kw) * 32] = make_ulonglong2(FA[kw], FB[kw]);
    }
    __syncthreads();

    // ---- Pass B: fwd H-DFT + weight + inv H-DFT, one kw column per warp ----
    {
        const int kw = role;

        // fold1 straight from pair loads
        ull E[7], OS[7];
        const ulonglong2 pr0 = bufc[(0 * 8 + kw) * 32];
        #pragma unroll
        for (int j = 1; j <= 6; ++j) {
            const ulonglong2 pr = bufc[(j * 8 + kw) * 32];
            E[j]  = f2add(pr.x, pr.y);
            OS[j] = swp(f2sub(pr.x, pr.y));
        }
        const ull fbp = f2add(pr0.x, pr0.y);
        const ull fbm = f2sub(pr0.x, pr0.y);
        // fold2
        ull EP[4], EM[4], OSM[4], OSP[4];
        #pragma unroll
        for (int j = 1; j <= 3; ++j) {
            EP[j]  = f2add(E[j],  E[7 - j]);
            EM[j]  = f2sub(E[j],  E[7 - j]);
            OSM[j] = f2sub(OS[j], OS[7 - j]);
            OSP[j] = f2add(OS[j], OS[7 - j]);
        }

        const float2* wt2c = reinterpret_cast<const float2*>(wt) + c;

        // forward per kh-pair: T = (Si,-Sr); X[kh]=C+T, X[14-kh]=C-T
        ull X0, X7, EZ[7], OZS[7];
        #pragma unroll
        for (int kh = 0; kh < 8; ++kh) {
            ull Cacc = (kh & 1) ? fbm : fbp;
            ull Tacc = 0ull;
            #pragma unroll
            for (int j = 1; j <= 3; ++j) {
                const int m = (kh * j) % 14;
                Cacc = f2fma((kh & 1) ? EM[j] : EP[j], CP(COS14[m]), Cacc);
                if ((kh % 7) != 0)
                    Tacc = f2fma((kh & 1) ? OSP[j] : OSM[j],
                                 pkc(SIN14[m], -SIN14[m]), Tacc);
            }
            ull Xa = cmulw(f2add(Cacc, Tacc),
                           pk(wt2c[(kh * 8 + kw) * CC].x,
                              wt2c[(kh * 8 + kw) * CC].y));
            if (kh == 0)      X0 = Xa;
            else if (kh == 7) X7 = Xa;
            else {
                ull Xb = cmulw(f2sub(Cacc, Tacc),
                               pk(wt2c[((14 - kh) * 8 + kw) * CC].x,
                                  wt2c[((14 - kh) * 8 + kw) * CC].y));
                EZ[kh]  = f2add(Xa, Xb);
                OZS[kh] = swp(f2sub(Xa, Xb));
            }
        }
        // inverse: fold2 on EZ/OZS, 3-term sums, store (Y_h, Y_{14-h}) pairs
        const ull ibp = f2add(X0, X7);
        const ull ibm = f2sub(X0, X7);
        ull EZP[4], EZM[4], OZM[4], OZP[4];
        #pragma unroll
        for (int j = 1; j <= 3; ++j) {
            EZP[j] = f2add(EZ[j],  EZ[7 - j]);
            EZM[j] = f2sub(EZ[j],  EZ[7 - j]);
            OZM[j] = f2sub(OZS[j], OZS[7 - j]);
            OZP[j] = f2add(OZS[j], OZS[7 - j]);
        }
        ull Y0sav = 0ull;
        #pragma unroll
        for (int h = 0; h < 8; ++h) {
            ull Cacc = (h & 1) ? ibm : ibp;
            ull Tacc = 0ull;
            #pragma unroll
            for (int j = 1; j <= 3; ++j) {
                const int m = (j * h) % 14;
                Cacc = f2fma((h & 1) ? EZM[j] : EZP[j], CP(COS14[m]), Cacc);
                if ((h % 7) != 0)
                    Tacc = f2fma((h & 1) ? OZP[j] : OZM[j],
                                 pkc(SIN14[m], -SIN14[m]), Tacc);
            }
            if (h == 0)       Y0sav = Cacc;                 // T = 0 at h = 0
            else if (h == 7)  bufc[(0 * 8 + kw) * 32] =
                                  make_ulonglong2(Y0sav, Cacc);  // (Y0, Y7)
            else
                bufc[(h * 8 + kw) * 32] =
                    make_ulonglong2(f2sub(Cacc, Tacc), f2add(Cacc, Tacc));
        }
    }
    __syncthreads();

    // ---- Pass C: c2r for both rows of pair p (pair loads) -------------------
    if (role < 7) {
        float* yb = y + base;
        ull yvA[8], yvB[8];
        #pragma unroll
        for (int kw = 0; kw < 8; ++kw) {
            const ulonglong2 v = bufc[(role * 8 + kw) * 32];
            yvA[kw] = v.x; yvB[kw] = v.y;
        }
        c2r_row(yb, hA, yvA);
        c2r_row(yb, hB, yvB);
    }
}

extern "C" void kernel_launch(void* const* d_in, const int* in_sizes, int n_in,
                              void* d_out, int out_size)
{
    (void)in_sizes; (void)n_in; (void)out_size;
    const float* x  = (const float*)d_in[0];
    const float* wt = (const float*)d_in[1];
    float* y        = (float*)d_out;

    const int smem_bytes = 56 * CB * (int)sizeof(ulonglong2); // 28672
    dim3 grid(CC / CB, 128); // (24, 128)
    gfilter_kernel<<<grid, NTH, smem_bytes>>>(x, wt, y);
}